// round 2
// baseline (speedup 1.0000x reference)
#include <cuda_runtime.h>
#include <math.h>

#define N_NODES 131072
#define N_EDGES 1048576
#define F_DIM   32
#define H_DIM   128
#define G_NUM   512

// Output layout (float32, concatenated in reference return order)
#define OUT_A   0LL         // [512,5]
#define OUT_S   2560LL      // [512,1000]
#define OUT_T   514560LL    // [512,1000]
#define OUT_ACT 1026560LL   // [512,4]
#define OUT_V   1028608LL   // [512,1]

// ---------------- scratch (static device globals; no allocation) ----------
__device__ float d_h0[N_NODES * H_DIM];    // 64 MB
__device__ float d_msg[N_NODES * H_DIM];   // 64 MB
__device__ float d_gsum[G_NUM * H_DIM];
__device__ float d_s2[G_NUM * 64];
__device__ int   d_flag64;
__device__ int   d_cnt[N_NODES];
__device__ int   d_off[N_NODES + 1];
__device__ int   d_cur[N_NODES];
__device__ unsigned long long d_epack[N_EDGES];   // 8 MB: (w_bits<<32)|src

// ---------------- helpers -------------------------------------------------
__device__ __forceinline__ long long ldidx(const void* p, long long i, int f64) {
    if (f64) return ((const long long*)p)[i];
    return (long long)((const int*)p)[i];
}

__device__ __forceinline__ void red_add_v4(float* ptr, float a, float b, float c, float d) {
    asm volatile("red.global.add.v4.f32 [%0], {%1,%2,%3,%4};"
                 :: "l"(ptr), "f"(a), "f"(b), "f"(c), "f"(d) : "memory");
}

// ---------------- kernel 0: dtype detect ----------------------------------
__global__ void k_detect(const void* __restrict__ eidx) {
    if (threadIdx.x == 0 && blockIdx.x == 0) {
        const unsigned* p = (const unsigned*)eidx;
        int f = 1;
        for (int i = 0; i < 128; i++) {
            if (p[2 * i + 1] != 0u) { f = 0; break; }
        }
        d_flag64 = f;
    }
}

// ---------------- kernel 1: h0 = nf @ W_in; zero cnt/gsum -----------------
__global__ void k_h0(const float* __restrict__ nf, const float* __restrict__ Win) {
    __shared__ float sw[F_DIM * H_DIM];   // 16 KB
    int t = threadIdx.x;                  // 256
    #pragma unroll
    for (int i = 0; i < 16; i++) sw[t + i * 256] = Win[t + i * 256];
    __syncthreads();

    int idx = blockIdx.x * 256 + t;       // < N*H
    int n = idx >> 7, j = idx & 127;
    const float* x = nf + (long long)n * F_DIM;
    float acc = 0.f;
    #pragma unroll
    for (int k = 0; k < F_DIM; k++) acc += __ldg(x + k) * sw[k * H_DIM + j];
    d_h0[idx] = acc;
    if (idx < N_NODES) d_cnt[idx] = 0;
    if (idx < G_NUM * H_DIM) d_gsum[idx] = 0.f;
}

// ---------------- kernel 2a: degree histogram -----------------------------
__global__ void k_hist(const void* __restrict__ eidx) {
    const int f64 = d_flag64;
    int e = blockIdx.x * 256 + threadIdx.x;
    long long tgt = ldidx(eidx, (long long)N_EDGES + e, f64);
    atomicAdd(&d_cnt[tgt], 1);
}

// ---------------- kernel 2b: exclusive scan (single block) ----------------
__global__ void k_scan() {
    __shared__ int ssum[1024];
    int t = threadIdx.x;
    int base = t * 128;
    // pass 1: local total
    int s = 0;
    const int4* cp = (const int4*)(d_cnt + base);
    #pragma unroll 4
    for (int i = 0; i < 32; i++) { int4 c = cp[i]; s += c.x + c.y + c.z + c.w; }
    ssum[t] = s;
    __syncthreads();
    // Hillis-Steele inclusive scan over 1024 thread sums
    for (int off = 1; off < 1024; off <<= 1) {
        int v = (t >= off) ? ssum[t - off] : 0;
        __syncthreads();
        ssum[t] += v;
        __syncthreads();
    }
    int run = (t == 0) ? 0 : ssum[t - 1];
    // pass 2: write exclusive offsets
    for (int i = 0; i < 128; i++) {
        int c = d_cnt[base + i];
        d_off[base + i] = run;
        d_cur[base + i] = run;
        run += c;
    }
    if (t == 1023) d_off[N_NODES] = run;
}

// ---------------- kernel 2c: scatter edges into CSR order -----------------
__global__ void k_scatter(const void* __restrict__ eidx, const float* __restrict__ ew) {
    const int f64 = d_flag64;
    int e = blockIdx.x * 256 + threadIdx.x;
    long long src = ldidx(eidx, e, f64);
    long long tgt = ldidx(eidx, (long long)N_EDGES + e, f64);
    float w = __ldg(ew + e);
    int pos = atomicAdd(&d_cur[tgt], 1);
    d_epack[pos] = ((unsigned long long)__float_as_uint(w) << 32) | (unsigned)(int)src;
}

// ---------------- kernel 2d: gather-accumulate msg rows (no fp32 atomics) -
__global__ void k_gather() {
    int n = blockIdx.x * 8 + (threadIdx.x >> 5);
    int lane = threadIdx.x & 31;
    int s = d_off[n], e = d_off[n + 1];
    float4 acc0 = {0.f, 0.f, 0.f, 0.f};
    float4 acc1 = {0.f, 0.f, 0.f, 0.f};
    int i = s;
    for (; i + 1 < e; i += 2) {
        unsigned long long p0 = d_epack[i];
        unsigned long long p1 = d_epack[i + 1];
        int s0 = (int)(unsigned)p0; float w0 = __uint_as_float((unsigned)(p0 >> 32));
        int s1 = (int)(unsigned)p1; float w1 = __uint_as_float((unsigned)(p1 >> 32));
        float4 v0 = ((const float4*)(d_h0 + (size_t)s0 * H_DIM))[lane];
        float4 v1 = ((const float4*)(d_h0 + (size_t)s1 * H_DIM))[lane];
        acc0.x += v0.x * w0; acc0.y += v0.y * w0; acc0.z += v0.z * w0; acc0.w += v0.w * w0;
        acc1.x += v1.x * w1; acc1.y += v1.y * w1; acc1.z += v1.z * w1; acc1.w += v1.w * w1;
    }
    if (i < e) {
        unsigned long long p0 = d_epack[i];
        int s0 = (int)(unsigned)p0; float w0 = __uint_as_float((unsigned)(p0 >> 32));
        float4 v0 = ((const float4*)(d_h0 + (size_t)s0 * H_DIM))[lane];
        acc0.x += v0.x * w0; acc0.y += v0.y * w0; acc0.z += v0.z * w0; acc0.w += v0.w * w0;
    }
    acc0.x += acc1.x; acc0.y += acc1.y; acc0.z += acc1.z; acc0.w += acc1.w;
    ((float4*)(d_msg + (size_t)n * H_DIM))[lane] = acc0;
}

// ---------------- kernel 3: h = relu(h0 + msg@W_msg); pool into gsum ------
// Block tile 128x128, 256 threads, thread micro-tile 8x8.
__global__ __launch_bounds__(256) void k_gemm_pool(const float* __restrict__ Wmsg,
                                                   const void* __restrict__ batch) {
    __shared__ float As[32][132];   // [k][row], padded
    __shared__ float Bs[32][132];   // [k][col], padded
    const int f64 = d_flag64;
    int t = threadIdx.x;
    int rowBase = blockIdx.x * 128;
    int tc = t & 15, tr = t >> 4;         // 16x16 thread grid, each 8 cols x 8 rows

    float acc[8][8];
    #pragma unroll
    for (int i = 0; i < 8; i++)
        #pragma unroll
        for (int j = 0; j < 8; j++) acc[i][j] = 0.f;

    for (int k0 = 0; k0 < H_DIM; k0 += 32) {
        // A tile (transposed into smem): 128 rows x 32 k
        {
            int r = t >> 1, kb = (t & 1) * 16;
            const float4* mrow = (const float4*)(d_msg + (size_t)(rowBase + r) * H_DIM + k0 + kb);
            #pragma unroll
            for (int q = 0; q < 4; q++) {
                float4 v = mrow[q];
                As[kb + q * 4 + 0][r] = v.x;
                As[kb + q * 4 + 1][r] = v.y;
                As[kb + q * 4 + 2][r] = v.z;
                As[kb + q * 4 + 3][r] = v.w;
            }
        }
        // B tile: 32 k x 128 cols
        {
            int kk = t >> 3, cb = (t & 7) * 16;
            const float4* wrow = (const float4*)(Wmsg + (size_t)(k0 + kk) * H_DIM + cb);
            #pragma unroll
            for (int q = 0; q < 4; q++)
                *(float4*)&Bs[kk][cb + q * 4] = wrow[q];
        }
        __syncthreads();

        #pragma unroll
        for (int kk = 0; kk < 32; kk++) {
            float4 a0 = *(const float4*)&As[kk][tr * 8];
            float4 a1 = *(const float4*)&As[kk][tr * 8 + 4];
            float4 b0 = *(const float4*)&Bs[kk][tc * 8];
            float4 b1 = *(const float4*)&Bs[kk][tc * 8 + 4];
            float av[8] = {a0.x, a0.y, a0.z, a0.w, a1.x, a1.y, a1.z, a1.w};
            float bv[8] = {b0.x, b0.y, b0.z, b0.w, b1.x, b1.y, b1.z, b1.w};
            #pragma unroll
            for (int i = 0; i < 8; i++)
                #pragma unroll
                for (int j = 0; j < 8; j++) acc[i][j] += av[i] * bv[j];
        }
        __syncthreads();
    }

    // epilogue: add h0, relu, pool into per-graph sums
    int c0 = tc * 8;
    int r0 = rowBase + tr * 8;
    long long gid[8];
    #pragma unroll
    for (int i = 0; i < 8; i++) gid[i] = ldidx(batch, r0 + i, f64);

    bool same = true;
    #pragma unroll
    for (int i = 1; i < 8; i++) same = same && (gid[i] == gid[0]);

    if (same) {
        float sum[8];
        #pragma unroll
        for (int j = 0; j < 8; j++) sum[j] = 0.f;
        #pragma unroll
        for (int i = 0; i < 8; i++) {
            const float4* h0r = (const float4*)(d_h0 + (size_t)(r0 + i) * H_DIM + c0);
            float4 ha = h0r[0], hb = h0r[1];
            float hv[8] = {ha.x, ha.y, ha.z, ha.w, hb.x, hb.y, hb.z, hb.w};
            #pragma unroll
            for (int j = 0; j < 8; j++) sum[j] += fmaxf(acc[i][j] + hv[j], 0.f);
        }
        float* base = d_gsum + gid[0] * H_DIM + c0;
        red_add_v4(base,     sum[0], sum[1], sum[2], sum[3]);
        red_add_v4(base + 4, sum[4], sum[5], sum[6], sum[7]);
    } else {
        #pragma unroll
        for (int i = 0; i < 8; i++) {
            const float4* h0r = (const float4*)(d_h0 + (size_t)(r0 + i) * H_DIM + c0);
            float4 ha = h0r[0], hb = h0r[1];
            float hv[8] = {ha.x, ha.y, ha.z, ha.w, hb.x, hb.y, hb.z, hb.w};
            float v[8];
            #pragma unroll
            for (int j = 0; j < 8; j++) v[j] = fmaxf(acc[i][j] + hv[j], 0.f);
            float* base = d_gsum + gid[i] * H_DIM + c0;
            red_add_v4(base,     v[0], v[1], v[2], v[3]);
            red_add_v4(base + 4, v[4], v[5], v[6], v[7]);
        }
    }
}

// ---------------- kernel 4a: per-graph backbone + small heads -------------
__global__ void k_head_small(const void* __restrict__ batch,
                             const float* __restrict__ W1, const float* __restrict__ W2,
                             const float* __restrict__ Wa, const float* __restrict__ Wact,
                             const float* __restrict__ Wv1, const float* __restrict__ Wv2,
                             float* __restrict__ out) {
    __shared__ float sg[128], s1[128], ss[64], v1s[32];
    const int f64 = d_flag64;
    int g = blockIdx.x, t = threadIdx.x;

    // node count for graph g via binary search over sorted batch
    int lo = 0, hi = N_NODES;
    while (lo < hi) { int mid = (lo + hi) >> 1; if (ldidx(batch, mid, f64) < (long long)g) lo = mid + 1; else hi = mid; }
    int start = lo;
    hi = N_NODES;
    while (lo < hi) { int mid = (lo + hi) >> 1; if (ldidx(batch, mid, f64) < (long long)g + 1) lo = mid + 1; else hi = mid; }
    int cnt = lo - start;
    float inv = (cnt > 0) ? 1.f / (float)cnt : 0.f;

    sg[t] = d_gsum[g * H_DIM + t] * inv;
    __syncthreads();

    // s1 = relu(g @ (W1_top + W1_bot))   (cat([g,g]) fold)
    {
        float acc = 0.f;
        #pragma unroll 4
        for (int k = 0; k < 128; k++)
            acc += sg[k] * (__ldg(W1 + k * 128 + t) + __ldg(W1 + (k + 128) * 128 + t));
        s1[t] = fmaxf(acc, 0.f);
    }
    __syncthreads();

    // s2 = relu(s1 @ W2)  [64]
    if (t < 64) {
        float acc = 0.f;
        #pragma unroll 4
        for (int k = 0; k < 128; k++) acc += s1[k] * __ldg(W2 + k * 64 + t);
        acc = fmaxf(acc, 0.f);
        ss[t] = acc;
        d_s2[g * 64 + t] = acc;
    }
    __syncthreads();

    if (t < 5) {                       // action_type
        float acc = 0.f;
        #pragma unroll
        for (int k = 0; k < 64; k++) acc += ss[k] * __ldg(Wa + k * 5 + t);
        out[OUT_A + g * 5 + t] = acc;
    } else if (t >= 32 && t < 36) {    // activation_logits
        int j = t - 32; float acc = 0.f;
        #pragma unroll
        for (int k = 0; k < 64; k++) acc += ss[k] * __ldg(Wact + k * 4 + j);
        out[OUT_ACT + g * 4 + j] = acc;
    } else if (t >= 64 && t < 96) {    // value hidden
        int j = t - 64; float acc = 0.f;
        #pragma unroll
        for (int k = 0; k < 64; k++) acc += ss[k] * __ldg(Wv1 + k * 32 + j);
        v1s[j] = fmaxf(acc, 0.f);
    }
    __syncthreads();
    if (t == 0) {                      // value = tanh(v1 @ Wv2)
        float acc = 0.f;
        #pragma unroll
        for (int k = 0; k < 32; k++) acc += v1s[k] * __ldg(Wv2 + k);
        out[OUT_V + g] = tanhf(acc);
    }
}

// ---------------- kernel 4b: big heads (source/target logits) -------------
__global__ void k_head_big(const float* __restrict__ Ws, const float* __restrict__ Wt,
                           float* __restrict__ out) {
    __shared__ float s2s[8][64];
    int gbase = blockIdx.x * 8;
    const float* W = blockIdx.y ? Wt : Ws;
    long long off = blockIdx.y ? OUT_T : OUT_S;
    int t = threadIdx.x;

    for (int i = t; i < 512; i += 128) s2s[i >> 6][i & 63] = d_s2[gbase * 64 + i];
    __syncthreads();

    for (int m = t; m < 1000; m += 128) {
        float acc[8];
        #pragma unroll
        for (int g8 = 0; g8 < 8; g8++) acc[g8] = 0.f;
        #pragma unroll 8
        for (int k = 0; k < 64; k++) {
            float wv = __ldg(W + k * 1000 + m);
            #pragma unroll
            for (int g8 = 0; g8 < 8; g8++) acc[g8] += s2s[g8][k] * wv;
        }
        #pragma unroll
        for (int g8 = 0; g8 < 8; g8++)
            out[off + (long long)(gbase + g8) * 1000 + m] = acc[g8];
    }
}

// ---------------- launch ---------------------------------------------------
extern "C" void kernel_launch(void* const* d_in, const int* in_sizes, int n_in,
                              void* d_out, int out_size) {
    const float* nf   = (const float*)d_in[0];
    const void*  eidx = d_in[1];
    const float* ew   = (const float*)d_in[2];
    // d_in[3] = layer_positions (unused)
    const void*  batch = d_in[4];
    int wb = n_in - 10;
    const float* Win  = (const float*)d_in[wb + 0];
    const float* Wmsg = (const float*)d_in[wb + 1];
    const float* W1   = (const float*)d_in[wb + 2];
    const float* W2   = (const float*)d_in[wb + 3];
    const float* Wa   = (const float*)d_in[wb + 4];
    const float* Ws   = (const float*)d_in[wb + 5];
    const float* Wt   = (const float*)d_in[wb + 6];
    const float* Wact = (const float*)d_in[wb + 7];
    const float* Wv1  = (const float*)d_in[wb + 8];
    const float* Wv2  = (const float*)d_in[wb + 9];
    float* out = (float*)d_out;

    k_detect<<<1, 32>>>(eidx);
    k_h0<<<(N_NODES * H_DIM) / 256, 256>>>(nf, Win);
    k_hist<<<N_EDGES / 256, 256>>>(eidx);
    k_scan<<<1, 1024>>>();
    k_scatter<<<N_EDGES / 256, 256>>>(eidx, ew);
    k_gather<<<N_NODES / 8, 256>>>();
    k_gemm_pool<<<N_NODES / 128, 256>>>(Wmsg, batch);
    k_head_small<<<G_NUM, 128>>>(batch, W1, W2, Wa, Wact, Wv1, Wv2, out);
    k_head_big<<<dim3(64, 2), 128>>>(Ws, Wt, out);
}

// round 3
// speedup vs baseline: 1.5071x; 1.5071x over previous
#include <cuda_runtime.h>
#include <math.h>

#define N_NODES 131072
#define N_EDGES 1048576
#define F_DIM   32
#define H_DIM   128
#define G_NUM   512

// Output layout (float32, concatenated in reference return order)
#define OUT_A   0LL         // [512,5]
#define OUT_S   2560LL      // [512,1000]
#define OUT_T   514560LL    // [512,1000]
#define OUT_ACT 1026560LL   // [512,4]
#define OUT_V   1028608LL   // [512,1]

// ---------------- scratch (static device globals; no allocation) ----------
__device__ float d_h0[N_NODES * H_DIM];    // 64 MB
__device__ float d_msg[N_NODES * H_DIM];   // 64 MB
__device__ float d_gsum[G_NUM * H_DIM];
__device__ float d_s2[G_NUM * 64];
__device__ int   d_flag64;
__device__ int   d_cnt[N_NODES];
__device__ int   d_off[N_NODES + 1];
__device__ int   d_cur[N_NODES];
__device__ int   d_bsum[512];
__device__ int   d_bbase[512];
__device__ unsigned long long d_epack[N_EDGES];   // 8 MB: (w_bits<<32)|src

// ---------------- helpers -------------------------------------------------
__device__ __forceinline__ long long ldidx(const void* p, long long i, int f64) {
    if (f64) return ((const long long*)p)[i];
    return (long long)((const int*)p)[i];
}

__device__ __forceinline__ void red_add_v4(float* ptr, float a, float b, float c, float d) {
    asm volatile("red.global.add.v4.f32 [%0], {%1,%2,%3,%4};"
                 :: "l"(ptr), "f"(a), "f"(b), "f"(c), "f"(d) : "memory");
}

// ---------------- kernel 0: dtype detect ----------------------------------
__global__ void k_detect(const void* __restrict__ eidx) {
    if (threadIdx.x == 0 && blockIdx.x == 0) {
        const unsigned* p = (const unsigned*)eidx;
        int f = 1;
        for (int i = 0; i < 128; i++) {
            if (p[2 * i + 1] != 0u) { f = 0; break; }
        }
        d_flag64 = f;
    }
}

// ---------------- kernel 1: h0 = nf @ W_in; zero cnt/gsum -----------------
__global__ void k_h0(const float* __restrict__ nf, const float* __restrict__ Win) {
    __shared__ float sw[F_DIM * H_DIM];   // 16 KB
    int t = threadIdx.x;                  // 256
    #pragma unroll
    for (int i = 0; i < 16; i++) sw[t + i * 256] = Win[t + i * 256];
    __syncthreads();

    int idx = blockIdx.x * 256 + t;       // < N*H
    int n = idx >> 7, j = idx & 127;
    const float* x = nf + (long long)n * F_DIM;
    float acc = 0.f;
    #pragma unroll
    for (int k = 0; k < F_DIM; k++) acc += __ldg(x + k) * sw[k * H_DIM + j];
    d_h0[idx] = acc;
    if (idx < N_NODES) d_cnt[idx] = 0;
    if (idx < G_NUM * H_DIM) d_gsum[idx] = 0.f;
}

// ---------------- kernel 2a: degree histogram -----------------------------
__global__ void k_hist(const void* __restrict__ eidx) {
    const int f64 = d_flag64;
    int e = blockIdx.x * 256 + threadIdx.x;
    long long tgt = ldidx(eidx, (long long)N_EDGES + e, f64);
    atomicAdd(&d_cnt[tgt], 1);
}

// ---------------- kernel 2b: hierarchical exclusive scan ------------------
// stage 1: per-block (256 elems) exclusive scan + block totals
__global__ void k_scan1() {
    __shared__ int wsum[8];
    int t = threadIdx.x;
    int i = blockIdx.x * 256 + t;
    int lane = t & 31, wid = t >> 5;
    int c = d_cnt[i];
    // warp inclusive scan
    int v = c;
    #pragma unroll
    for (int off = 1; off < 32; off <<= 1) {
        int u = __shfl_up_sync(0xffffffffu, v, off);
        if (lane >= off) v += u;
    }
    if (lane == 31) wsum[wid] = v;
    __syncthreads();
    if (t < 8) {
        int w = wsum[t];
        // tiny inclusive scan of 8 warp totals
        #pragma unroll
        for (int off = 1; off < 8; off <<= 1) {
            int u = __shfl_up_sync(0xffu, w, off);
            if (t >= off) w += u;
        }
        wsum[t] = w;
    }
    __syncthreads();
    int warpBase = (wid == 0) ? 0 : wsum[wid - 1];
    d_off[i] = warpBase + v - c;          // local exclusive (no block base yet)
    if (t == 255) d_bsum[blockIdx.x] = wsum[7];
}

// stage 2: exclusive scan of 512 block totals (1 block, trivially small)
__global__ void k_scan2() {
    __shared__ int s[512];
    int t = threadIdx.x;
    s[t] = d_bsum[t];
    __syncthreads();
    #pragma unroll
    for (int off = 1; off < 512; off <<= 1) {
        int v = (t >= off) ? s[t - off] : 0;
        __syncthreads();
        s[t] += v;
        __syncthreads();
    }
    d_bbase[t] = (t == 0) ? 0 : s[t - 1];
    if (t == 0) d_off[N_NODES] = N_EDGES;   // total is a constant
}

// stage 3: add block base, init cursors
__global__ void k_scan3() {
    int i = blockIdx.x * 256 + threadIdx.x;
    int v = d_off[i] + d_bbase[blockIdx.x];
    d_off[i] = v;
    d_cur[i] = v;
}

// ---------------- kernel 2c: scatter edges into CSR order -----------------
__global__ void k_scatter(const void* __restrict__ eidx, const float* __restrict__ ew) {
    const int f64 = d_flag64;
    int e = blockIdx.x * 256 + threadIdx.x;
    long long src = ldidx(eidx, e, f64);
    long long tgt = ldidx(eidx, (long long)N_EDGES + e, f64);
    float w = __ldg(ew + e);
    int pos = atomicAdd(&d_cur[tgt], 1);
    d_epack[pos] = ((unsigned long long)__float_as_uint(w) << 32) | (unsigned)(int)src;
}

// ---------------- kernel 2d: gather-accumulate msg rows (no fp32 atomics) -
__global__ void k_gather() {
    int n = blockIdx.x * 8 + (threadIdx.x >> 5);
    int lane = threadIdx.x & 31;
    int s = d_off[n], e = d_off[n + 1];
    float4 acc0 = {0.f, 0.f, 0.f, 0.f};
    float4 acc1 = {0.f, 0.f, 0.f, 0.f};
    float4 acc2 = {0.f, 0.f, 0.f, 0.f};
    float4 acc3 = {0.f, 0.f, 0.f, 0.f};
    int i = s;
    for (; i + 3 < e; i += 4) {
        unsigned long long p0 = d_epack[i];
        unsigned long long p1 = d_epack[i + 1];
        unsigned long long p2 = d_epack[i + 2];
        unsigned long long p3 = d_epack[i + 3];
        int s0 = (int)(unsigned)p0; float w0 = __uint_as_float((unsigned)(p0 >> 32));
        int s1 = (int)(unsigned)p1; float w1 = __uint_as_float((unsigned)(p1 >> 32));
        int s2 = (int)(unsigned)p2; float w2 = __uint_as_float((unsigned)(p2 >> 32));
        int s3 = (int)(unsigned)p3; float w3 = __uint_as_float((unsigned)(p3 >> 32));
        float4 v0 = ((const float4*)(d_h0 + (size_t)s0 * H_DIM))[lane];
        float4 v1 = ((const float4*)(d_h0 + (size_t)s1 * H_DIM))[lane];
        float4 v2 = ((const float4*)(d_h0 + (size_t)s2 * H_DIM))[lane];
        float4 v3 = ((const float4*)(d_h0 + (size_t)s3 * H_DIM))[lane];
        acc0.x += v0.x * w0; acc0.y += v0.y * w0; acc0.z += v0.z * w0; acc0.w += v0.w * w0;
        acc1.x += v1.x * w1; acc1.y += v1.y * w1; acc1.z += v1.z * w1; acc1.w += v1.w * w1;
        acc2.x += v2.x * w2; acc2.y += v2.y * w2; acc2.z += v2.z * w2; acc2.w += v2.w * w2;
        acc3.x += v3.x * w3; acc3.y += v3.y * w3; acc3.z += v3.z * w3; acc3.w += v3.w * w3;
    }
    for (; i < e; i++) {
        unsigned long long p0 = d_epack[i];
        int s0 = (int)(unsigned)p0; float w0 = __uint_as_float((unsigned)(p0 >> 32));
        float4 v0 = ((const float4*)(d_h0 + (size_t)s0 * H_DIM))[lane];
        acc0.x += v0.x * w0; acc0.y += v0.y * w0; acc0.z += v0.z * w0; acc0.w += v0.w * w0;
    }
    acc0.x += acc1.x + acc2.x + acc3.x;
    acc0.y += acc1.y + acc2.y + acc3.y;
    acc0.z += acc1.z + acc2.z + acc3.z;
    acc0.w += acc1.w + acc2.w + acc3.w;
    ((float4*)(d_msg + (size_t)n * H_DIM))[lane] = acc0;
}

// ---------------- kernel 3: h = relu(h0 + msg@W_msg); pool into gsum ------
// Block tile 128x128, 256 threads, thread micro-tile 8x8.
__global__ __launch_bounds__(256) void k_gemm_pool(const float* __restrict__ Wmsg,
                                                   const void* __restrict__ batch) {
    __shared__ float As[32][132];   // [k][row], padded
    __shared__ float Bs[32][132];   // [k][col], padded
    const int f64 = d_flag64;
    int t = threadIdx.x;
    int rowBase = blockIdx.x * 128;
    int tc = t & 15, tr = t >> 4;         // 16x16 thread grid, each 8 cols x 8 rows

    float acc[8][8];
    #pragma unroll
    for (int i = 0; i < 8; i++)
        #pragma unroll
        for (int j = 0; j < 8; j++) acc[i][j] = 0.f;

    for (int k0 = 0; k0 < H_DIM; k0 += 32) {
        // A tile (transposed into smem): 128 rows x 32 k
        {
            int r = t >> 1, kb = (t & 1) * 16;
            const float4* mrow = (const float4*)(d_msg + (size_t)(rowBase + r) * H_DIM + k0 + kb);
            #pragma unroll
            for (int q = 0; q < 4; q++) {
                float4 v = mrow[q];
                As[kb + q * 4 + 0][r] = v.x;
                As[kb + q * 4 + 1][r] = v.y;
                As[kb + q * 4 + 2][r] = v.z;
                As[kb + q * 4 + 3][r] = v.w;
            }
        }
        // B tile: 32 k x 128 cols
        {
            int kk = t >> 3, cb = (t & 7) * 16;
            const float4* wrow = (const float4*)(Wmsg + (size_t)(k0 + kk) * H_DIM + cb);
            #pragma unroll
            for (int q = 0; q < 4; q++)
                *(float4*)&Bs[kk][cb + q * 4] = wrow[q];
        }
        __syncthreads();

        #pragma unroll
        for (int kk = 0; kk < 32; kk++) {
            float4 a0 = *(const float4*)&As[kk][tr * 8];
            float4 a1 = *(const float4*)&As[kk][tr * 8 + 4];
            float4 b0 = *(const float4*)&Bs[kk][tc * 8];
            float4 b1 = *(const float4*)&Bs[kk][tc * 8 + 4];
            float av[8] = {a0.x, a0.y, a0.z, a0.w, a1.x, a1.y, a1.z, a1.w};
            float bv[8] = {b0.x, b0.y, b0.z, b0.w, b1.x, b1.y, b1.z, b1.w};
            #pragma unroll
            for (int i = 0; i < 8; i++)
                #pragma unroll
                for (int j = 0; j < 8; j++) acc[i][j] += av[i] * bv[j];
        }
        __syncthreads();
    }

    // epilogue: add h0, relu, pool into per-graph sums
    int c0 = tc * 8;
    int r0 = rowBase + tr * 8;
    long long gid[8];
    #pragma unroll
    for (int i = 0; i < 8; i++) gid[i] = ldidx(batch, r0 + i, f64);

    bool same = true;
    #pragma unroll
    for (int i = 1; i < 8; i++) same = same && (gid[i] == gid[0]);

    if (same) {
        float sum[8];
        #pragma unroll
        for (int j = 0; j < 8; j++) sum[j] = 0.f;
        #pragma unroll
        for (int i = 0; i < 8; i++) {
            const float4* h0r = (const float4*)(d_h0 + (size_t)(r0 + i) * H_DIM + c0);
            float4 ha = h0r[0], hb = h0r[1];
            float hv[8] = {ha.x, ha.y, ha.z, ha.w, hb.x, hb.y, hb.z, hb.w};
            #pragma unroll
            for (int j = 0; j < 8; j++) sum[j] += fmaxf(acc[i][j] + hv[j], 0.f);
        }
        float* base = d_gsum + gid[0] * H_DIM + c0;
        red_add_v4(base,     sum[0], sum[1], sum[2], sum[3]);
        red_add_v4(base + 4, sum[4], sum[5], sum[6], sum[7]);
    } else {
        #pragma unroll
        for (int i = 0; i < 8; i++) {
            const float4* h0r = (const float4*)(d_h0 + (size_t)(r0 + i) * H_DIM + c0);
            float4 ha = h0r[0], hb = h0r[1];
            float hv[8] = {ha.x, ha.y, ha.z, ha.w, hb.x, hb.y, hb.z, hb.w};
            float v[8];
            #pragma unroll
            for (int j = 0; j < 8; j++) v[j] = fmaxf(acc[i][j] + hv[j], 0.f);
            float* base = d_gsum + gid[i] * H_DIM + c0;
            red_add_v4(base,     v[0], v[1], v[2], v[3]);
            red_add_v4(base + 4, v[4], v[5], v[6], v[7]);
        }
    }
}

// ---------------- kernel 4a: per-graph backbone + small heads -------------
__global__ void k_head_small(const void* __restrict__ batch,
                             const float* __restrict__ W1, const float* __restrict__ W2,
                             const float* __restrict__ Wa, const float* __restrict__ Wact,
                             const float* __restrict__ Wv1, const float* __restrict__ Wv2,
                             float* __restrict__ out) {
    __shared__ float sg[128], s1[128], ss[64], v1s[32];
    const int f64 = d_flag64;
    int g = blockIdx.x, t = threadIdx.x;

    // node count for graph g via binary search over sorted batch
    int lo = 0, hi = N_NODES;
    while (lo < hi) { int mid = (lo + hi) >> 1; if (ldidx(batch, mid, f64) < (long long)g) lo = mid + 1; else hi = mid; }
    int start = lo;
    hi = N_NODES;
    while (lo < hi) { int mid = (lo + hi) >> 1; if (ldidx(batch, mid, f64) < (long long)g + 1) lo = mid + 1; else hi = mid; }
    int cnt = lo - start;
    float inv = (cnt > 0) ? 1.f / (float)cnt : 0.f;

    sg[t] = d_gsum[g * H_DIM + t] * inv;
    __syncthreads();

    // s1 = relu(g @ (W1_top + W1_bot))   (cat([g,g]) fold)
    {
        float acc = 0.f;
        #pragma unroll 4
        for (int k = 0; k < 128; k++)
            acc += sg[k] * (__ldg(W1 + k * 128 + t) + __ldg(W1 + (k + 128) * 128 + t));
        s1[t] = fmaxf(acc, 0.f);
    }
    __syncthreads();

    // s2 = relu(s1 @ W2)  [64]
    if (t < 64) {
        float acc = 0.f;
        #pragma unroll 4
        for (int k = 0; k < 128; k++) acc += s1[k] * __ldg(W2 + k * 64 + t);
        acc = fmaxf(acc, 0.f);
        ss[t] = acc;
        d_s2[g * 64 + t] = acc;
    }
    __syncthreads();

    if (t < 5) {                       // action_type
        float acc = 0.f;
        #pragma unroll
        for (int k = 0; k < 64; k++) acc += ss[k] * __ldg(Wa + k * 5 + t);
        out[OUT_A + g * 5 + t] = acc;
    } else if (t >= 32 && t < 36) {    // activation_logits
        int j = t - 32; float acc = 0.f;
        #pragma unroll
        for (int k = 0; k < 64; k++) acc += ss[k] * __ldg(Wact + k * 4 + j);
        out[OUT_ACT + g * 4 + j] = acc;
    } else if (t >= 64 && t < 96) {    // value hidden
        int j = t - 64; float acc = 0.f;
        #pragma unroll
        for (int k = 0; k < 64; k++) acc += ss[k] * __ldg(Wv1 + k * 32 + j);
        v1s[j] = fmaxf(acc, 0.f);
    }
    __syncthreads();
    if (t == 0) {                      // value = tanh(v1 @ Wv2)
        float acc = 0.f;
        #pragma unroll
        for (int k = 0; k < 32; k++) acc += v1s[k] * __ldg(Wv2 + k);
        out[OUT_V + g] = tanhf(acc);
    }
}

// ---------------- kernel 4b: big heads (source/target logits) -------------
__global__ void k_head_big(const float* __restrict__ Ws, const float* __restrict__ Wt,
                           float* __restrict__ out) {
    __shared__ float s2s[8][64];
    int gbase = blockIdx.x * 8;
    const float* W = blockIdx.y ? Wt : Ws;
    long long off = blockIdx.y ? OUT_T : OUT_S;
    int t = threadIdx.x;

    for (int i = t; i < 512; i += 128) s2s[i >> 6][i & 63] = d_s2[gbase * 64 + i];
    __syncthreads();

    for (int m = t; m < 1000; m += 128) {
        float acc[8];
        #pragma unroll
        for (int g8 = 0; g8 < 8; g8++) acc[g8] = 0.f;
        #pragma unroll 8
        for (int k = 0; k < 64; k++) {
            float wv = __ldg(W + k * 1000 + m);
            #pragma unroll
            for (int g8 = 0; g8 < 8; g8++) acc[g8] += s2s[g8][k] * wv;
        }
        #pragma unroll
        for (int g8 = 0; g8 < 8; g8++)
            out[off + (long long)(gbase + g8) * 1000 + m] = acc[g8];
    }
}

// ---------------- launch ---------------------------------------------------
extern "C" void kernel_launch(void* const* d_in, const int* in_sizes, int n_in,
                              void* d_out, int out_size) {
    const float* nf   = (const float*)d_in[0];
    const void*  eidx = d_in[1];
    const float* ew   = (const float*)d_in[2];
    // d_in[3] = layer_positions (unused)
    const void*  batch = d_in[4];
    int wb = n_in - 10;
    const float* Win  = (const float*)d_in[wb + 0];
    const float* Wmsg = (const float*)d_in[wb + 1];
    const float* W1   = (const float*)d_in[wb + 2];
    const float* W2   = (const float*)d_in[wb + 3];
    const float* Wa   = (const float*)d_in[wb + 4];
    const float* Ws   = (const float*)d_in[wb + 5];
    const float* Wt   = (const float*)d_in[wb + 6];
    const float* Wact = (const float*)d_in[wb + 7];
    const float* Wv1  = (const float*)d_in[wb + 8];
    const float* Wv2  = (const float*)d_in[wb + 9];
    float* out = (float*)d_out;

    k_detect<<<1, 32>>>(eidx);
    k_h0<<<(N_NODES * H_DIM) / 256, 256>>>(nf, Win);
    k_hist<<<N_EDGES / 256, 256>>>(eidx);
    k_scan1<<<N_NODES / 256, 256>>>();
    k_scan2<<<1, 512>>>();
    k_scan3<<<N_NODES / 256, 256>>>();
    k_scatter<<<N_EDGES / 256, 256>>>(eidx, ew);
    k_gather<<<N_NODES / 8, 256>>>();
    k_gemm_pool<<<N_NODES / 128, 256>>>(Wmsg, batch);
    k_head_small<<<G_NUM, 128>>>(batch, W1, W2, Wa, Wact, Wv1, Wv2, out);
    k_head_big<<<dim3(64, 2), 128>>>(Ws, Wt, out);
}